// round 7
// baseline (speedup 1.0000x reference)
#include <cuda_runtime.h>
#include <cuda_bf16.h>

// Problem constants
#define BATCH 16
#define CH    512
#define HW    48
#define NPIX  2304          // 48*48
#define IDIM  64            // inter channels

// ---------------------------------------------------------------------------
// Device scratch (allocation-free rule: __device__ globals)
// ---------------------------------------------------------------------------
__device__ float g_q[(size_t)BATCH * IDIM * NPIX];   //  9.4 MB
__device__ float g_k[(size_t)BATCH * IDIM * NPIX];   //  9.4 MB
__device__ float g_v[(size_t)BATCH * CH   * NPIX];   // 75.5 MB
__device__ float g_s[(size_t)BATCH * NPIX * NPIX];   // 339.7 MB

// ===========================================================================
// TF32 helpers
// ===========================================================================
__device__ __forceinline__ unsigned f2tf32(float x) {
    unsigned r;
    asm("cvt.rna.tf32.f32 %0, %1;" : "=r"(r) : "f"(x));
    return r;
}

__device__ __forceinline__ void mma_tf32(float* c, const unsigned* a,
                                         unsigned b0, unsigned b1) {
    asm volatile(
        "mma.sync.aligned.m16n8k8.row.col.f32.tf32.tf32.f32 "
        "{%0,%1,%2,%3}, {%4,%5,%6,%7}, {%8,%9}, {%0,%1,%2,%3};"
        : "+f"(c[0]), "+f"(c[1]), "+f"(c[2]), "+f"(c[3])
        : "r"(a[0]), "r"(a[1]), "r"(a[2]), "r"(a[3]), "r"(b0), "r"(b1));
}

// Fragment-major smem offsets for mma.m16n8k8 (tf32).
// A fragment: lane = (m%8)*4 + (k%4); reg = (k/4)*2 + ((m%16)/8)
__device__ __forceinline__ int fragA_off(int m, int k) {
    int mt = m >> 4, mr = m & 15;
    int kc = k >> 3, kr = k & 7;
    int lane = ((mr & 7) << 2) | (kr & 3);
    int reg  = ((kr >> 2) << 1) | (mr >> 3);
    return ((kc * 8 + mt) * 32 + lane) * 4 + reg;
}
// B fragment: lane = (n%8)*4 + (k%4); reg = k/4
__device__ __forceinline__ int fragB_off(int n, int k) {
    int nt = n >> 3, nr = n & 7;
    int kc = k >> 3, kr = k & 7;
    int lane = (nr << 2) | (kr & 3);
    int reg  = (kr >> 2);
    return ((kc * 16 + nt) * 32 + lane) * 2 + reg;
}

// ===========================================================================
// fp32 SIMT GEMM — used only for q,k projections (M=64, needs guards, tiny).
// ===========================================================================
template <bool A_KM, bool B_KM>
__global__ void __launch_bounds__(256)
gemm_kernel(const float* __restrict__ A, int lda, long long strideA,
            const float* __restrict__ B, int ldb, long long strideB,
            float* __restrict__ C, int ldc, long long strideC,
            int M, int N, int K)
{
    constexpr int BM = 128, BN = 128, BK = 16, TM = 8, TN = 8;
    __shared__ float As[BK][BM + 4];
    __shared__ float Bs[BK][BN + 4];

    const int b = blockIdx.z;
    A += (size_t)b * strideA;
    B += (size_t)b * strideB;
    C += (size_t)b * strideC;

    const int tid  = threadIdx.x;
    const int tx   = tid & 15;
    const int ty   = tid >> 4;
    const int row0 = blockIdx.y * BM;
    const int col0 = blockIdx.x * BN;

    float acc[TM][TN] = {};

    for (int kt = 0; kt < K; kt += BK) {
        if (A_KM) {
            #pragma unroll
            for (int i = tid; i < BM * BK; i += 256) {
                int m = i >> 4, kk = i & 15, gm = row0 + m;
                As[kk][m] = (gm < M) ? A[(size_t)gm * lda + (kt + kk)] : 0.0f;
            }
        } else {
            #pragma unroll
            for (int i = tid; i < BK * BM; i += 256) {
                int kk = i >> 7, m = i & 127, gm = row0 + m;
                As[kk][m] = (gm < M) ? A[(size_t)(kt + kk) * lda + gm] : 0.0f;
            }
        }
        if (B_KM) {
            #pragma unroll
            for (int i = tid; i < BN * BK; i += 256) {
                int n = i >> 4, kk = i & 15;
                Bs[kk][n] = B[(size_t)(col0 + n) * ldb + (kt + kk)];
            }
        } else {
            #pragma unroll
            for (int i = tid; i < BK * BN; i += 256) {
                int kk = i >> 7, n = i & 127;
                Bs[kk][n] = B[(size_t)(kt + kk) * ldb + (col0 + n)];
            }
        }
        __syncthreads();

        #pragma unroll
        for (int kk = 0; kk < BK; kk++) {
            float af[TM], bf[TN];
            #pragma unroll
            for (int i = 0; i < TM; i++) af[i] = As[kk][ty * TM + i];
            #pragma unroll
            for (int j = 0; j < TN; j++) bf[j] = Bs[kk][tx * TN + j];
            #pragma unroll
            for (int i = 0; i < TM; i++)
                #pragma unroll
                for (int j = 0; j < TN; j++)
                    acc[i][j] += af[i] * bf[j];
        }
        __syncthreads();
    }

    #pragma unroll
    for (int i = 0; i < TM; i++) {
        int gm = row0 + ty * TM + i;
        if (gm >= M) continue;
        #pragma unroll
        for (int j = 0; j < TN; j++)
            C[(size_t)gm * ldc + (col0 + tx * TN + j)] = acc[i][j];
    }
}

// ===========================================================================
// TF32 tensor GEMM, fragment-major smem, register double-buffered.
// Requires M%128==0, N%128==0, K%32==0, lda/ldb/ldc%4==0 (all call sites).
// Block 128x128, BK=32, 8 warps (4x2), warp tile 32x64.
// ===========================================================================
template <bool A_KM, bool B_KM, bool EPI>
__global__ void __launch_bounds__(256)
gemm_tf32_kernel(const float* __restrict__ A, int lda, long long strideA,
                 const float* __restrict__ B, int ldb, long long strideB,
                 float* __restrict__ C, int ldc, long long strideC,
                 int K,
                 const float* __restrict__ gamma,
                 const float* __restrict__ X, long long strideX)
{
    constexpr int BK = 32;              // 4 kc-steps of k8
    __shared__ unsigned As[4096];       // [kc 4][mt 8][lane 32][4]
    __shared__ unsigned Bs[4096];       // [kc 4][nt 16][lane 32][2]

    const int b = blockIdx.z;
    A += (size_t)b * strideA;
    B += (size_t)b * strideB;
    C += (size_t)b * strideC;

    const int tid  = threadIdx.x;
    const int warp = tid >> 5, lane = tid & 31;
    const int gid  = lane >> 2, tig = lane & 3;
    const int wm   = warp >> 1, wn = warp & 1;
    const int row0 = blockIdx.y * 128;
    const int col0 = blockIdx.x * 128;

    float acc[2][8][4] = {};
    float4 pa[4], pb[4];

    // ---- prologue: load k-tile 0 ----
    #pragma unroll
    for (int it = 0; it < 4; it++) {
        int s = tid + it * 256;
        if (A_KM) { int m = s >> 3, kq = s & 7;
            pa[it] = *(const float4*)&A[(size_t)(row0 + m) * lda + kq * 4];
        } else    { int k = s >> 5, mq = s & 31;
            pa[it] = *(const float4*)&A[(size_t)k * lda + row0 + mq * 4];
        }
        if (B_KM) { int n = s >> 3, kq = s & 7;
            pb[it] = *(const float4*)&B[(size_t)(col0 + n) * ldb + kq * 4];
        } else    { int k = s >> 5, nq = s & 31;
            pb[it] = *(const float4*)&B[(size_t)k * ldb + col0 + nq * 4];
        }
    }
    #pragma unroll
    for (int it = 0; it < 4; it++) {
        int s = tid + it * 256;
        float va[4] = {pa[it].x, pa[it].y, pa[it].z, pa[it].w};
        float vb[4] = {pb[it].x, pb[it].y, pb[it].z, pb[it].w};
        if (A_KM) { int m = s >> 3, k0 = (s & 7) * 4;
            #pragma unroll
            for (int j = 0; j < 4; j++) As[fragA_off(m, k0 + j)] = f2tf32(va[j]);
        } else    { int k = s >> 5, m0 = (s & 31) * 4;
            #pragma unroll
            for (int j = 0; j < 4; j++) As[fragA_off(m0 + j, k)] = f2tf32(va[j]);
        }
        if (B_KM) { int n = s >> 3, k0 = (s & 7) * 4;
            #pragma unroll
            for (int j = 0; j < 4; j++) Bs[fragB_off(n, k0 + j)] = f2tf32(vb[j]);
        } else    { int k = s >> 5, n0 = (s & 31) * 4;
            #pragma unroll
            for (int j = 0; j < 4; j++) Bs[fragB_off(n0 + j, k)] = f2tf32(vb[j]);
        }
    }
    __syncthreads();

    // ---- main loop ----
    for (int kt = BK; kt <= K; kt += BK) {
        const bool more = (kt < K);
        if (more) {
            #pragma unroll
            for (int it = 0; it < 4; it++) {
                int s = tid + it * 256;
                if (A_KM) { int m = s >> 3, kq = s & 7;
                    pa[it] = *(const float4*)&A[(size_t)(row0 + m) * lda + kt + kq * 4];
                } else    { int k = s >> 5, mq = s & 31;
                    pa[it] = *(const float4*)&A[(size_t)(kt + k) * lda + row0 + mq * 4];
                }
                if (B_KM) { int n = s >> 3, kq = s & 7;
                    pb[it] = *(const float4*)&B[(size_t)(col0 + n) * ldb + kt + kq * 4];
                } else    { int k = s >> 5, nq = s & 31;
                    pb[it] = *(const float4*)&B[(size_t)(kt + k) * ldb + col0 + nq * 4];
                }
            }
        }

        #pragma unroll
        for (int kc = 0; kc < 4; kc++) {
            uint4 a0 = *(const uint4*)&As[((kc * 8 + wm * 2 + 0) * 32 + lane) * 4];
            uint4 a1 = *(const uint4*)&As[((kc * 8 + wm * 2 + 1) * 32 + lane) * 4];
            #pragma unroll
            for (int nt = 0; nt < 8; nt++) {
                uint2 bb = *(const uint2*)&Bs[((kc * 16 + wn * 8 + nt) * 32 + lane) * 2];
                mma_tf32(acc[0][nt], (const unsigned*)&a0, bb.x, bb.y);
                mma_tf32(acc[1][nt], (const unsigned*)&a1, bb.x, bb.y);
            }
        }

        if (more) {
            __syncthreads();
            #pragma unroll
            for (int it = 0; it < 4; it++) {
                int s = tid + it * 256;
                float va[4] = {pa[it].x, pa[it].y, pa[it].z, pa[it].w};
                float vb[4] = {pb[it].x, pb[it].y, pb[it].z, pb[it].w};
                if (A_KM) { int m = s >> 3, k0 = (s & 7) * 4;
                    #pragma unroll
                    for (int j = 0; j < 4; j++) As[fragA_off(m, k0 + j)] = f2tf32(va[j]);
                } else    { int k = s >> 5, m0 = (s & 31) * 4;
                    #pragma unroll
                    for (int j = 0; j < 4; j++) As[fragA_off(m0 + j, k)] = f2tf32(va[j]);
                }
                if (B_KM) { int n = s >> 3, k0 = (s & 7) * 4;
                    #pragma unroll
                    for (int j = 0; j < 4; j++) Bs[fragB_off(n, k0 + j)] = f2tf32(vb[j]);
                } else    { int k = s >> 5, n0 = (s & 31) * 4;
                    #pragma unroll
                    for (int j = 0; j < 4; j++) Bs[fragB_off(n0 + j, k)] = f2tf32(vb[j]);
                }
            }
            __syncthreads();
        }
    }

    // ---- epilogue (float2 stores) ----
    const float g  = EPI ? gamma[0] : 0.0f;
    const float* Xb = EPI ? (X + (size_t)b * strideX) : nullptr;
    #pragma unroll
    for (int mt = 0; mt < 2; mt++) {
        #pragma unroll
        for (int half = 0; half < 2; half++) {
            int gm = row0 + wm * 32 + mt * 16 + gid + half * 8;
            #pragma unroll
            for (int nt = 0; nt < 8; nt++) {
                int gn = col0 + wn * 64 + nt * 8 + tig * 2;
                float r0 = acc[mt][nt][half * 2 + 0];
                float r1 = acc[mt][nt][half * 2 + 1];
                if (EPI) {
                    float2 xv = *(const float2*)&Xb[(size_t)gm * ldc + gn];
                    r0 = g * r0 + xv.x;
                    r1 = g * r1 + xv.y;
                }
                float2 rv = {r0, r1};
                *(float2*)&C[(size_t)gm * ldc + gn] = rv;
            }
        }
    }
}

// ===========================================================================
// Scores kernel: S[n,m] = sum_i q[i,n]*k[i,m], tf32x2 (hi/lo split) for
// near-fp32 accuracy (softmax logits). K = IDIM = 64 in 4 chunks of 16.
// Block 128x128 tile of S, grid (18,18,16).
// ===========================================================================
__global__ void __launch_bounds__(256)
scores_tf32x2_kernel(const float* __restrict__ Q, const float* __restrict__ Km,
                     float* __restrict__ S)
{
    constexpr int BK = 16;              // 2 kc-steps per chunk
    __shared__ unsigned Ah[2048], Al[2048];
    __shared__ unsigned Bh[2048], Bl[2048];

    const int b = blockIdx.z;
    const float* Aq = Q  + (size_t)b * IDIM * NPIX;
    const float* Bk = Km + (size_t)b * IDIM * NPIX;
    float* Sb = S + (size_t)b * NPIX * NPIX;

    const int tid  = threadIdx.x;
    const int warp = tid >> 5, lane = tid & 31;
    const int gid  = lane >> 2, tig = lane & 3;
    const int wm   = warp >> 1, wn = warp & 1;
    const int row0 = blockIdx.y * 128;
    const int col0 = blockIdx.x * 128;

    float acc[2][8][4] = {};
    float4 pa[2], pb[2];

    // prologue: chunk 0
    #pragma unroll
    for (int it = 0; it < 2; it++) {
        int s = tid + it * 256;
        int k = s >> 5, mq = s & 31;
        pa[it] = *(const float4*)&Aq[(size_t)k * NPIX + row0 + mq * 4];
        pb[it] = *(const float4*)&Bk[(size_t)k * NPIX + col0 + mq * 4];
    }
    #pragma unroll
    for (int it = 0; it < 2; it++) {
        int s = tid + it * 256;
        int k = s >> 5, m0 = (s & 31) * 4;
        float va[4] = {pa[it].x, pa[it].y, pa[it].z, pa[it].w};
        float vb[4] = {pb[it].x, pb[it].y, pb[it].z, pb[it].w};
        #pragma unroll
        for (int j = 0; j < 4; j++) {
            int oa = fragA_off(m0 + j, k);
            unsigned h = f2tf32(va[j]);
            Ah[oa] = h;
            Al[oa] = f2tf32(va[j] - __uint_as_float(h));
            int ob = fragB_off(m0 + j, k);
            unsigned hb = f2tf32(vb[j]);
            Bh[ob] = hb;
            Bl[ob] = f2tf32(vb[j] - __uint_as_float(hb));
        }
    }
    __syncthreads();

    for (int kt = BK; kt <= IDIM; kt += BK) {
        const bool more = (kt < IDIM);
        if (more) {
            #pragma unroll
            for (int it = 0; it < 2; it++) {
                int s = tid + it * 256;
                int k = s >> 5, mq = s & 31;
                pa[it] = *(const float4*)&Aq[(size_t)(kt + k) * NPIX + row0 + mq * 4];
                pb[it] = *(const float4*)&Bk[(size_t)(kt + k) * NPIX + col0 + mq * 4];
            }
        }

        #pragma unroll
        for (int kc = 0; kc < 2; kc++) {
            uint4 ah0 = *(const uint4*)&Ah[((kc * 8 + wm * 2 + 0) * 32 + lane) * 4];
            uint4 ah1 = *(const uint4*)&Ah[((kc * 8 + wm * 2 + 1) * 32 + lane) * 4];
            uint4 al0 = *(const uint4*)&Al[((kc * 8 + wm * 2 + 0) * 32 + lane) * 4];
            uint4 al1 = *(const uint4*)&Al[((kc * 8 + wm * 2 + 1) * 32 + lane) * 4];
            #pragma unroll
            for (int nt = 0; nt < 8; nt++) {
                uint2 bh = *(const uint2*)&Bh[((kc * 16 + wn * 8 + nt) * 32 + lane) * 2];
                uint2 bl = *(const uint2*)&Bl[((kc * 16 + wn * 8 + nt) * 32 + lane) * 2];
                // acc += ah*bh + ah*bl + al*bh   (drop al*bl: ~2^-22)
                mma_tf32(acc[0][nt], (const unsigned*)&ah0, bh.x, bh.y);
                mma_tf32(acc[1][nt], (const unsigned*)&ah1, bh.x, bh.y);
                mma_tf32(acc[0][nt], (const unsigned*)&ah0, bl.x, bl.y);
                mma_tf32(acc[1][nt], (const unsigned*)&ah1, bl.x, bl.y);
                mma_tf32(acc[0][nt], (const unsigned*)&al0, bh.x, bh.y);
                mma_tf32(acc[1][nt], (const unsigned*)&al1, bh.x, bh.y);
            }
        }

        if (more) {
            __syncthreads();
            #pragma unroll
            for (int it = 0; it < 2; it++) {
                int s = tid + it * 256;
                int k = s >> 5, m0 = (s & 31) * 4;
                float va[4] = {pa[it].x, pa[it].y, pa[it].z, pa[it].w};
                float vb[4] = {pb[it].x, pb[it].y, pb[it].z, pb[it].w};
                #pragma unroll
                for (int j = 0; j < 4; j++) {
                    int oa = fragA_off(m0 + j, k);
                    unsigned h = f2tf32(va[j]);
                    Ah[oa] = h;
                    Al[oa] = f2tf32(va[j] - __uint_as_float(h));
                    int ob = fragB_off(m0 + j, k);
                    unsigned hb = f2tf32(vb[j]);
                    Bh[ob] = hb;
                    Bl[ob] = f2tf32(vb[j] - __uint_as_float(hb));
                }
            }
            __syncthreads();
        }
    }

    // epilogue: plain stores
    #pragma unroll
    for (int mt = 0; mt < 2; mt++) {
        #pragma unroll
        for (int half = 0; half < 2; half++) {
            int gm = row0 + wm * 32 + mt * 16 + gid + half * 8;
            #pragma unroll
            for (int nt = 0; nt < 8; nt++) {
                int gn = col0 + wn * 64 + nt * 8 + tig * 2;
                float2 rv = {acc[mt][nt][half * 2 + 0], acc[mt][nt][half * 2 + 1]};
                *(float2*)&Sb[(size_t)gm * NPIX + gn] = rv;
            }
        }
    }
}

// ---------------------------------------------------------------------------
// Row softmax over last dim of S[b][n][m]. 2304 floats = 576 float4 =
// 192 threads x 3 float4 -> whole row in registers, one read + one write.
// ---------------------------------------------------------------------------
__global__ void __launch_bounds__(192)
softmax_kernel(float* __restrict__ S)
{
    const int n = blockIdx.x;
    const int b = blockIdx.y;
    float* row = S + ((size_t)b * NPIX + n) * NPIX;

    const int tid  = threadIdx.x;
    const int lane = tid & 31;
    const int warp = tid >> 5;     // 0..5

    float4 v[3];
    float mx = -1e30f;
    #pragma unroll
    for (int j = 0; j < 3; j++) {
        v[j] = *(const float4*)&row[(tid + j * 192) * 4];
        mx = fmaxf(fmaxf(fmaxf(v[j].x, v[j].y), fmaxf(v[j].z, v[j].w)), mx);
    }

    __shared__ float smax[6];
    __shared__ float ssum[6];
    __shared__ float sbc[2];

    #pragma unroll
    for (int o = 16; o > 0; o >>= 1)
        mx = fmaxf(mx, __shfl_xor_sync(0xffffffffu, mx, o));
    if (lane == 0) smax[warp] = mx;
    __syncthreads();
    if (tid == 0) {
        float m = smax[0];
        #pragma unroll
        for (int i = 1; i < 6; i++) m = fmaxf(m, smax[i]);
        sbc[0] = m;
    }
    __syncthreads();
    mx = sbc[0];

    float s = 0.0f;
    #pragma unroll
    for (int j = 0; j < 3; j++) {
        v[j].x = __expf(v[j].x - mx);
        v[j].y = __expf(v[j].y - mx);
        v[j].z = __expf(v[j].z - mx);
        v[j].w = __expf(v[j].w - mx);
        s += (v[j].x + v[j].y) + (v[j].z + v[j].w);
    }
    #pragma unroll
    for (int o = 16; o > 0; o >>= 1)
        s += __shfl_xor_sync(0xffffffffu, s, o);
    if (lane == 0) ssum[warp] = s;
    __syncthreads();
    if (tid == 0) {
        float t = ssum[0];
        #pragma unroll
        for (int i = 1; i < 6; i++) t += ssum[i];
        sbc[1] = 1.0f / t;
    }
    __syncthreads();
    const float inv = sbc[1];

    #pragma unroll
    for (int j = 0; j < 3; j++) {
        v[j].x *= inv; v[j].y *= inv; v[j].z *= inv; v[j].w *= inv;
        *(float4*)&row[(tid + j * 192) * 4] = v[j];
    }
}

// ---------------------------------------------------------------------------
// kernel_launch: x, Wq, Wk, Wv, gamma  ->  out (fp32, B*C*H*W)
// ---------------------------------------------------------------------------
extern "C" void kernel_launch(void* const* d_in, const int* in_sizes, int n_in,
                              void* d_out, int out_size)
{
    const float* x     = (const float*)d_in[0];
    const float* Wq    = (const float*)d_in[1];
    const float* Wk    = (const float*)d_in[2];
    const float* Wv    = (const float*)d_in[3];
    const float* gamma = (const float*)d_in[4];
    float* out = (float*)d_out;

    float *qp, *kp, *vp, *sp;
    cudaGetSymbolAddress((void**)&qp, g_q);
    cudaGetSymbolAddress((void**)&kp, g_k);
    cudaGetSymbolAddress((void**)&vp, g_v);
    cudaGetSymbolAddress((void**)&sp, g_s);

    const long long sx = (long long)CH * NPIX;
    const long long sq = (long long)IDIM * NPIX;
    const long long ss = (long long)NPIX * NPIX;
    const int NB = NPIX / 128;   // 18

    // q = Wq @ x  (fp32 SIMT, M=64)
    gemm_kernel<true, false><<<dim3(NB, 1, BATCH), 256>>>(
        Wq, CH, 0, x, NPIX, sx, qp, NPIX, sq, IDIM, NPIX, CH);

    // k = Wk @ x  (fp32 SIMT, M=64)
    gemm_kernel<true, false><<<dim3(NB, 1, BATCH), 256>>>(
        Wk, CH, 0, x, NPIX, sx, kp, NPIX, sq, IDIM, NPIX, CH);

    // v = Wv @ x  (tf32 tensor, fragment-major)
    gemm_tf32_kernel<true, false, false><<<dim3(NB, CH / 128, BATCH), 256>>>(
        Wv, CH, 0, x, NPIX, sx, vp, NPIX, sx,
        CH, nullptr, nullptr, 0);

    // S[n,m] = q . k  (tf32x2 — near-fp32 logits)
    scores_tf32x2_kernel<<<dim3(NB, NB, BATCH), 256>>>(qp, kp, sp);

    // softmax over m
    softmax_kernel<<<dim3(NPIX, BATCH), 192>>>(sp);

    // out = gamma * (v @ P^T) + x  (tf32 tensor, fragment-major)
    gemm_tf32_kernel<true, true, true><<<dim3(NB, CH / 128, BATCH), 256>>>(
        vp, NPIX, sx, sp, NPIX, ss, out, NPIX, sx,
        NPIX, gamma, x, sx);
}